// round 1
// baseline (speedup 1.0000x reference)
#include <cuda_runtime.h>
#include <math.h>

// Split-KV (flash-decoding) stage-2 merge.
// Shapes fixed by the problem: B=256, H=32, S=16, D=128, fp32.
//
// out[b,h,d] = sum_s w[b,h,s] * att_out[b,h,s,d] / sum_s w[b,h,s]
//   w = exp(lse - max_valid(lse)), valid iff per_split*s < seq_len
//   per_split = ceil(ceil(seq_len/splits)/32)*32
//
// One warp per (b,h): lanes 0..15 handle LSE stats via shuffles,
// every lane owns one float4 slice of D (32*4 = 128).
// Invalid splits are skipped entirely (saves ~half the 64MB att_out read).

#define B_DIM 256
#define H_DIM 32
#define S_DIM 16
#define D_DIM 128
#define MIN_BLOCK_KV 32

__global__ __launch_bounds__(256, 8)
void splitkv_merge_kernel(const float* __restrict__ att_out,
                          const float* __restrict__ att_lse,
                          const int*   __restrict__ kv_indptr,
                          const int*   __restrict__ num_kv_splits,
                          float*       __restrict__ out)
{
    const int warp_id = (blockIdx.x * blockDim.x + threadIdx.x) >> 5;
    const int lane    = threadIdx.x & 31;
    if (warp_id >= B_DIM * H_DIM) return;

    const int b = warp_id / H_DIM;       // batch
    // (h is implicit in warp_id; att_out/att_lse/out index by warp_id directly)

    // ---- per-batch split geometry (warp-uniform) ----
    const int seq_len = kv_indptr[b + 1] - kv_indptr[b];
    const int splits  = num_kv_splits[b];
    // per_split = ceil(ceil(seq_len/splits)/32)*32
    const int per_split = ((((seq_len + splits - 1) / splits) + MIN_BLOCK_KV - 1)
                           / MIN_BLOCK_KV) * MIN_BLOCK_KV;

    // ---- LSE stats: lanes 0..15 hold one split each ----
    const long lse_base = (long)warp_id * S_DIM;
    float lse = -INFINITY;
    bool  valid = false;
    if (lane < S_DIM) {
        valid = ((long)per_split * lane) < (long)seq_len;
        if (valid) lse = att_lse[lse_base + lane];
    }

    // warp max over all 32 lanes (lanes >=16 contribute -inf)
    float m = lse;
    #pragma unroll
    for (int o = 16; o > 0; o >>= 1)
        m = fmaxf(m, __shfl_xor_sync(0xffffffffu, m, o));

    // weights (exp(-inf - m) -> 0 for invalid lanes)
    float w = valid ? expf(lse - m) : 0.0f;

    float esum = w;
    #pragma unroll
    for (int o = 16; o > 0; o >>= 1)
        esum += __shfl_xor_sync(0xffffffffu, esum, o);
    const float inv_esum = 1.0f / esum;

    // ---- weighted accumulation over splits ----
    // att_out rows for this (b,h): S_DIM x D_DIM floats, contiguous.
    const float4* __restrict__ src =
        reinterpret_cast<const float4*>(att_out + (long)warp_id * (S_DIM * D_DIM));

    float4 acc = make_float4(0.f, 0.f, 0.f, 0.f);
    #pragma unroll
    for (int s = 0; s < S_DIM; ++s) {
        const float ws = __shfl_sync(0xffffffffu, w, s);
        // warp-uniform branch: skip loads for invalid / zero-weight splits
        if (ws != 0.0f) {
            const float4 v = src[s * (D_DIM / 4) + lane];
            acc.x = fmaf(ws, v.x, acc.x);
            acc.y = fmaf(ws, v.y, acc.y);
            acc.z = fmaf(ws, v.z, acc.z);
            acc.w = fmaf(ws, v.w, acc.w);
        }
    }

    acc.x *= inv_esum;
    acc.y *= inv_esum;
    acc.z *= inv_esum;
    acc.w *= inv_esum;

    float4* __restrict__ dst =
        reinterpret_cast<float4*>(out + (long)warp_id * D_DIM);
    dst[lane] = acc;
}

extern "C" void kernel_launch(void* const* d_in, const int* in_sizes, int n_in,
                              void* d_out, int out_size)
{
    const float* att_out       = (const float*)d_in[0];
    const float* att_lse       = (const float*)d_in[1];
    // d_in[2] = q        (unused by the merge)
    // d_in[3] = v_buffer (unused by the merge)
    const int*   kv_indptr     = (const int*)d_in[4];
    const int*   num_kv_splits = (const int*)d_in[5];
    float*       out           = (float*)d_out;

    // 8192 warps total, 8 warps (256 threads) per block -> 1024 blocks
    const int total_warps = B_DIM * H_DIM;
    const int threads = 256;
    const int blocks = (total_warps * 32 + threads - 1) / threads;
    splitkv_merge_kernel<<<blocks, threads>>>(att_out, att_lse,
                                              kv_indptr, num_kv_splits, out);
}